// round 14
// baseline (speedup 1.0000x reference)
#include <cuda_runtime.h>
#include <cstdint>

#define NUM_USERS 100000
#define NUM_ITEMS 50000
#define NN 150000          // N_NODES
#define NE 4000000         // N_EDGES
#define H 64
#define BATCH 100000
#define MLPH 32
#define NTILES ((NN + 1023) / 1024)   // 147

#define TILES_TOT 9375     // NN / 16
#define GEMM_GRID 444
#define GEMM_SMEM (2 * 64 * 132 * 4)   // 67584 B: Bhi + Blo, padded rows

// ---- scratch (allocation-free: __device__ globals) ----
__device__ __align__(256) float g_xa[NN * H];
__device__ __align__(256) float g_xb[NN * H];
__device__ __align__(256) float g_mean[NN * H];
__device__ int g_cnt[NN];      // zero at load (BSS); k_scan1 re-zeroes after reading
__device__ int g_off[NN + 1];
__device__ int g_cur[NN];
__device__ int g_srcs[NE];
__device__ int g_psum[NTILES];

// ============================================================
// tf32 helpers
// ============================================================
__device__ __forceinline__ uint32_t f2tf32(float f) {
    uint32_t r;
    asm("cvt.rna.tf32.f32 %0, %1;" : "=r"(r) : "f"(f));
    return r;
}
__device__ __forceinline__ void mma_tf32(float c[4],
        uint32_t a0, uint32_t a1, uint32_t a2, uint32_t a3,
        uint32_t b0, uint32_t b1) {
    asm volatile("mma.sync.aligned.m16n8k8.row.col.f32.tf32.tf32.f32 "
        "{%0,%1,%2,%3}, {%4,%5,%6,%7}, {%8,%9}, {%0,%1,%2,%3};"
        : "+f"(c[0]), "+f"(c[1]), "+f"(c[2]), "+f"(c[3])
        : "r"(a0), "r"(a1), "r"(a2), "r"(a3), "r"(b0), "r"(b1));
}

// ============================================================
// 1) concat embeddings into g_xa (side stream, overlapped with CSR build)
// ============================================================
__global__ void k_concat(const float* __restrict__ ue, const float* __restrict__ ie) {
    int i = blockIdx.x * blockDim.x + threadIdx.x;
    const int nu4 = NUM_USERS * H / 4;   // 1,600,000
    const int ni4 = NUM_ITEMS * H / 4;   //   800,000
    float4* xa = (float4*)g_xa;
    if (i < nu4) {
        xa[i] = ((const float4*)ue)[i];
    } else if (i < nu4 + ni4) {
        xa[i] = ((const float4*)ie)[i - nu4];
    }
}

// ============================================================
// 2) degree count — 4 edges per thread (g_cnt zero at entry)
// ============================================================
__global__ void k_count(const int* __restrict__ dst) {
    int i = (blockIdx.x * blockDim.x + threadIdx.x) * 4;
    if (i < NE) {
        int4 d = *(const int4*)&dst[i];
        atomicAdd(&g_cnt[d.x], 1);
        atomicAdd(&g_cnt[d.y], 1);
        atomicAdd(&g_cnt[d.z], 1);
        atomicAdd(&g_cnt[d.w], 1);
    }
}

// ============================================================
// 3) scans (3-phase); scan1 re-zeroes g_cnt for the next call/replay
// ============================================================
__global__ void k_scan1() {
    __shared__ __align__(16) int sdata[1024];
    int tid = threadIdx.x;
    int i = blockIdx.x * 1024 + tid;
    int v = 0;
    if (i < NN) { v = g_cnt[i]; g_cnt[i] = 0; }
    sdata[tid] = v;
    __syncthreads();
    #pragma unroll
    for (int ofs = 1; ofs < 1024; ofs <<= 1) {
        int t = (tid >= ofs) ? sdata[tid - ofs] : 0;
        __syncthreads();
        sdata[tid] += t;
        __syncthreads();
    }
    if (i < NN) g_off[i] = sdata[tid] - v;
    if (tid == 1023) g_psum[blockIdx.x] = sdata[1023];
}

__global__ void k_scan2() {
    __shared__ __align__(16) int sdata[256];
    int tid = threadIdx.x;
    int v = (tid < NTILES) ? g_psum[tid] : 0;
    sdata[tid] = v;
    __syncthreads();
    #pragma unroll
    for (int ofs = 1; ofs < 256; ofs <<= 1) {
        int t = (tid >= ofs) ? sdata[tid - ofs] : 0;
        __syncthreads();
        sdata[tid] += t;
        __syncthreads();
    }
    if (tid < NTILES) g_psum[tid] = sdata[tid] - v;
}

__global__ void k_scan3() {
    int i = blockIdx.x * blockDim.x + threadIdx.x;
    if (i < NN) {
        int o = g_off[i] + g_psum[blockIdx.x >> 2];
        g_off[i] = o;
        g_cur[i] = o;
    }
    if (i == 0) g_off[NN] = NE;
}

// ============================================================
// 4) bucket edges by dst — 4 edges per thread
// ============================================================
__global__ void k_bucket(const int* __restrict__ src, const int* __restrict__ dst) {
    int i = (blockIdx.x * blockDim.x + threadIdx.x) * 4;
    if (i < NE) {
        int4 d = *(const int4*)&dst[i];
        int4 s = *(const int4*)&src[i];
        int p0 = atomicAdd(&g_cur[d.x], 1);
        int p1 = atomicAdd(&g_cur[d.y], 1);
        int p2 = atomicAdd(&g_cur[d.z], 1);
        int p3 = atomicAdd(&g_cur[d.w], 1);
        g_srcs[p0] = s.x;
        g_srcs[p1] = s.y;
        g_srcs[p2] = s.z;
        g_srcs[p3] = s.w;
    }
}

// ============================================================
// 5) mean aggregation over a node chunk [n0, n0+ncnt):
//    warp per node, float2 lanes, 4-deep unroll, __ldcg row loads
// ============================================================
__global__ void k_agg(const float* __restrict__ x, int n0, int ncnt) {
    int w = (blockIdx.x * blockDim.x + threadIdx.x) >> 5;
    if (w >= ncnt) return;
    w += n0;
    int lane = threadIdx.x & 31;
    const float2* x2p = (const float2*)x;
    int s = g_off[w], e = g_off[w + 1];
    float2 a0 = make_float2(0.f, 0.f), a1 = make_float2(0.f, 0.f);
    float2 a2 = make_float2(0.f, 0.f), a3 = make_float2(0.f, 0.f);
    int i = s;
    for (; i + 3 < e; i += 4) {
        int s0 = __ldg(&g_srcs[i]);
        int s1 = __ldg(&g_srcs[i + 1]);
        int s2 = __ldg(&g_srcs[i + 2]);
        int s3 = __ldg(&g_srcs[i + 3]);
        float2 v0 = __ldcg(&x2p[s0 * 32 + lane]);
        float2 v1 = __ldcg(&x2p[s1 * 32 + lane]);
        float2 v2 = __ldcg(&x2p[s2 * 32 + lane]);
        float2 v3 = __ldcg(&x2p[s3 * 32 + lane]);
        a0.x += v0.x; a0.y += v0.y;
        a1.x += v1.x; a1.y += v1.y;
        a2.x += v2.x; a2.y += v2.y;
        a3.x += v3.x; a3.y += v3.y;
    }
    for (; i < e; i++) {
        int sn = __ldg(&g_srcs[i]);
        float2 v = __ldcg(&x2p[sn * 32 + lane]);
        a0.x += v.x; a0.y += v.y;
    }
    int c = e - s;
    float inv = 1.0f / (float)(c > 1 ? c : 1);
    float2 m;
    m.x = ((a0.x + a1.x) + (a2.x + a3.x)) * inv;
    m.y = ((a0.y + a1.y) + (a2.y + a3.y)) * inv;
    ((float2*)g_mean)[w * 32 + lane] = m;
}

// ============================================================
// 6) tensor-core layer GEMM (3xTF32) over warp-tile range [t0, t0+tcnt):
//    xout = relu(mean @ Wl + xin @ Wr + b) — weights staged in smem
// ============================================================
__global__ __launch_bounds__(256) void k_gemm(
        const float* __restrict__ xin, float* __restrict__ xout,
        const float* __restrict__ Wl, const float* __restrict__ bl,
        const float* __restrict__ Wr, int t0, int tcnt) {
    extern __shared__ float smem[];
    float* sBhi = smem;              // [n=64][k=128] stride 132
    float* sBlo = smem + 64 * 132;

    int tid = threadIdx.x;
    for (int idx = tid; idx < 64 * 128; idx += 256) {
        int k = idx >> 6;
        int n = idx & 63;
        float v = (k < 64) ? Wl[k * 64 + n] : Wr[(k - 64) * 64 + n];
        uint32_t hb = f2tf32(v);
        float hi = __uint_as_float(hb);
        uint32_t lb = f2tf32(v - hi);
        sBhi[n * 132 + k] = __uint_as_float(hb);
        sBlo[n * 132 + k] = __uint_as_float(lb);
    }
    __syncthreads();

    int wid = tid >> 5, lane = tid & 31;
    int g = lane >> 2;
    int tig = lane & 3;

    float2 bias[8];
    #pragma unroll
    for (int n0 = 0; n0 < 8; n0++)
        bias[n0] = *(const float2*)&bl[n0 * 8 + 2 * tig];

    const float* Aops[2] = { g_mean, xin };
    int nwarp = gridDim.x * 8;

    for (int wt = blockIdx.x * 8 + wid; wt < tcnt; wt += nwarp) {
        int r0 = (t0 + wt) * 16;
        float c[8][4];
        #pragma unroll
        for (int n0 = 0; n0 < 8; n0++)
            c[n0][0] = c[n0][1] = c[n0][2] = c[n0][3] = 0.f;

        #pragma unroll
        for (int op = 0; op < 2; op++) {
            const float* A = Aops[op];
            int kb = op * 64;
            #pragma unroll
            for (int ks = 0; ks < 8; ks++) {
                int col = ks * 8 + tig;
                float f0 = __ldg(&A[(r0 + g) * 64 + col]);
                float f1 = __ldg(&A[(r0 + g + 8) * 64 + col]);
                float f2 = __ldg(&A[(r0 + g) * 64 + col + 4]);
                float f3 = __ldg(&A[(r0 + g + 8) * 64 + col + 4]);
                uint32_t ah0 = f2tf32(f0), ah1 = f2tf32(f1);
                uint32_t ah2 = f2tf32(f2), ah3 = f2tf32(f3);
                uint32_t al0 = f2tf32(f0 - __uint_as_float(ah0));
                uint32_t al1 = f2tf32(f1 - __uint_as_float(ah1));
                uint32_t al2 = f2tf32(f2 - __uint_as_float(ah2));
                uint32_t al3 = f2tf32(f3 - __uint_as_float(ah3));
                int kk = kb + ks * 8;
                #pragma unroll
                for (int n0 = 0; n0 < 8; n0++) {
                    int nrow = (n0 * 8 + g) * 132 + kk + tig;
                    uint32_t bh0 = __float_as_uint(sBhi[nrow]);
                    uint32_t bh1 = __float_as_uint(sBhi[nrow + 4]);
                    uint32_t bl0 = __float_as_uint(sBlo[nrow]);
                    uint32_t bl1 = __float_as_uint(sBlo[nrow + 4]);
                    mma_tf32(c[n0], ah0, ah1, ah2, ah3, bh0, bh1);
                    mma_tf32(c[n0], ah0, ah1, ah2, ah3, bl0, bl1);
                    mma_tf32(c[n0], al0, al1, al2, al3, bh0, bh1);
                }
            }
        }

        #pragma unroll
        for (int n0 = 0; n0 < 8; n0++) {
            float2 o01, o23;
            o01.x = fmaxf(c[n0][0] + bias[n0].x, 0.f);
            o01.y = fmaxf(c[n0][1] + bias[n0].y, 0.f);
            o23.x = fmaxf(c[n0][2] + bias[n0].x, 0.f);
            o23.y = fmaxf(c[n0][3] + bias[n0].y, 0.f);
            int ccol = n0 * 8 + 2 * tig;
            *(float2*)&xout[(r0 + g) * 64 + ccol] = o01;
            *(float2*)&xout[(r0 + g + 8) * 64 + ccol] = o23;
        }
    }
}

// ============================================================
// 7) final MLP: warp per pair
// ============================================================
__global__ void k_mlp(const float* __restrict__ x,
                      const int* __restrict__ uid, const int* __restrict__ iid,
                      const float* __restrict__ W1, const float* __restrict__ b1,
                      const float* __restrict__ W2, const float* __restrict__ b2,
                      float* __restrict__ out) {
    __shared__ __align__(16) float sW1[2 * H * MLPH];
    __shared__ __align__(16) float sW2[MLPH];
    __shared__ __align__(16) float sb1[MLPH];
    __shared__ float sb2;
    __shared__ __align__(16) float spair[8][2 * H];

    int tid = threadIdx.x;
    for (int i = tid; i < 2 * H * MLPH; i += 256) sW1[i] = W1[i];
    if (tid < MLPH) { sW2[tid] = W2[tid]; sb1[tid] = b1[tid]; }
    if (tid == 0) sb2 = b2[0];
    __syncthreads();

    int wid = tid >> 5, lane = tid & 31;
    for (int i = blockIdx.x * 8 + wid; i < BATCH; i += gridDim.x * 8) {
        int u = __ldg(&uid[i]);
        int it = __ldg(&iid[i]) + NUM_USERS;
        const float4* ur = (const float4*)(x + (size_t)u * H);
        const float4* ir = (const float4*)(x + (size_t)it * H);
        if (lane < 16) {
            *(float4*)&spair[wid][lane * 4] = __ldg(&ur[lane]);
        } else {
            *(float4*)&spair[wid][64 + (lane - 16) * 4] = __ldg(&ir[lane - 16]);
        }
        __syncwarp();
        float h = sb1[lane];
        #pragma unroll 16
        for (int k = 0; k < 2 * H; k++) {
            h += spair[wid][k] * sW1[k * MLPH + lane];
        }
        h = fmaxf(h, 0.f);
        float r = h * sW2[lane];
        #pragma unroll
        for (int o = 16; o; o >>= 1) r += __shfl_xor_sync(0xffffffffu, r, o);
        if (lane == 0) out[i] = fminf(fmaxf(r + sb2, 1.0f), 5.0f);
        __syncwarp();
    }
}

// ============================================================
// launch — minimal-footprint pipeline: 1 side stream, 3 reused events
// ============================================================
extern "C" void kernel_launch(void* const* d_in, const int* in_sizes, int n_in,
                              void* d_out, int out_size) {
    (void)in_sizes; (void)n_in; (void)out_size;
    const int*   edge = (const int*)d_in[0];
    const int*   src  = edge;
    const int*   dst  = edge + NE;
    const int*   uid  = (const int*)d_in[1];
    const int*   iid  = (const int*)d_in[2];
    const float* ue   = (const float*)d_in[3];
    const float* ie   = (const float*)d_in[4];
    const float* Wl   = (const float*)d_in[5];
    const float* bl   = (const float*)d_in[6];
    const float* Wr   = (const float*)d_in[7];
    const float* W1   = (const float*)d_in[8];
    const float* b1   = (const float*)d_in[9];
    const float* W2   = (const float*)d_in[10];
    const float* b2   = (const float*)d_in[11];
    float* out = (float*)d_out;

    float *xa, *xb;
    cudaGetSymbolAddress((void**)&xa, g_xa);
    cudaGetSymbolAddress((void**)&xb, g_xb);

    cudaFuncSetAttribute(k_gemm, cudaFuncAttributeMaxDynamicSharedMemorySize, GEMM_SMEM);

    // R11-proven footprint: ONE side stream + three event handles (reused)
    cudaStream_t s1;
    cudaStreamCreateWithFlags(&s1, cudaStreamNonBlocking);
    cudaEvent_t e0, eA, eG;
    cudaEventCreateWithFlags(&e0, cudaEventDisableTiming);
    cudaEventCreateWithFlags(&eA, cudaEventDisableTiming);
    cudaEventCreateWithFlags(&eG, cudaEventDisableTiming);

    // fork: concat on s1, CSR chain on stream 0
    cudaEventRecord(e0, 0);
    cudaStreamWaitEvent(s1, e0, 0);
    k_concat<<<(2400000 + 255) / 256, 256, 0, s1>>>(ue, ie);

    k_count<<<(NE / 4 + 255) / 256, 256>>>(dst);
    k_scan1<<<NTILES, 1024>>>();
    k_scan2<<<1, 256>>>();
    k_scan3<<<NTILES * 4, 256>>>();
    k_bucket<<<(NE / 4 + 255) / 256, 256>>>(src, dst);

    // s1 is free after concat; layer-0 agg (stream 0) must also see g_xa:
    cudaEventRecord(eG, s1);
    cudaStreamWaitEvent(0, eG, 0);

    // two chunks of warp-tiles
    const int tc0 = TILES_TOT / 2;            // 4687
    const int tc1 = TILES_TOT - tc0;          // 4688

    float* cur = xa;
    float* nxt = xb;
    for (int l = 0; l < 3; l++) {
        const float* lWl = Wl + l * H * H;
        const float* lbl = bl + l * H;
        const float* lWr = Wr + l * H * H;

        // chunk 0: agg on stream 0, gemm on s1 (hidden under agg chunk 1)
        k_agg<<<(tc0 * 16 * 32 + 255) / 256, 256>>>(cur, 0, tc0 * 16);
        cudaEventRecord(eA, 0);
        cudaStreamWaitEvent(s1, eA, 0);
        k_gemm<<<GEMM_GRID, 256, GEMM_SMEM, s1>>>(cur, nxt, lWl, lbl, lWr, 0, tc0);

        // chunk 1: agg on stream 0, gemm on stream 0 (tail)
        k_agg<<<(tc1 * 16 * 32 + 255) / 256, 256>>>(cur, tc0 * 16, tc1 * 16);
        k_gemm<<<GEMM_GRID, 256, GEMM_SMEM>>>(cur, nxt, lWl, lbl, lWr, tc0, tc1);

        // layer join: stream 0 must wait for chunk-0 gemm on s1
        cudaEventRecord(eG, s1);
        cudaStreamWaitEvent(0, eG, 0);
        float* t = cur; cur = nxt; nxt = t;
    }

    k_mlp<<<2048, 256>>>(cur, uid, iid, W1, b1, W2, b2, out);
}

// round 16
// speedup vs baseline: 1.0974x; 1.0974x over previous
#include <cuda_runtime.h>
#include <cstdint>

#define NUM_USERS 100000
#define NUM_ITEMS 50000
#define NN 150000          // N_NODES
#define NE 4000000         // N_EDGES
#define H 64
#define BATCH 100000
#define MLPH 32
#define NTILES ((NN + 1023) / 1024)   // 147

#define GEMM_GRID 444
#define GEMM_SMEM (2 * 64 * 132 * 4)   // 67584 B: Bhi + Blo, padded rows

#define MLP_TILES (BATCH / 16)         // 6250
#define MLP_GRID 782                   // 782*8 = 6256 warps >= 6250 tiles
// smem: W1hi[32][132] + W1lo[32][132] + spair[8][16][132]
#define MLP_SMEM ((2 * 32 * 132 + 8 * 16 * 132) * 4)   // 101376 B

// ---- scratch (allocation-free: __device__ globals) ----
__device__ __align__(256) float g_xa[NN * H];
__device__ __align__(256) float g_xb[NN * H];
__device__ __align__(256) float g_mean[NN * H];
__device__ int g_cnt[NN];      // zero at load (BSS); k_scan1 re-zeroes after reading
__device__ int g_off[NN + 1];
__device__ int g_cur[NN];
__device__ int g_srcs[NE];
__device__ int g_psum[NTILES];

// ============================================================
// tf32 helpers
// ============================================================
__device__ __forceinline__ uint32_t f2tf32(float f) {
    uint32_t r;
    asm("cvt.rna.tf32.f32 %0, %1;" : "=r"(r) : "f"(f));
    return r;
}
__device__ __forceinline__ void mma_tf32(float c[4],
        uint32_t a0, uint32_t a1, uint32_t a2, uint32_t a3,
        uint32_t b0, uint32_t b1) {
    asm volatile("mma.sync.aligned.m16n8k8.row.col.f32.tf32.tf32.f32 "
        "{%0,%1,%2,%3}, {%4,%5,%6,%7}, {%8,%9}, {%0,%1,%2,%3};"
        : "+f"(c[0]), "+f"(c[1]), "+f"(c[2]), "+f"(c[3])
        : "r"(a0), "r"(a1), "r"(a2), "r"(a3), "r"(b0), "r"(b1));
}

// ============================================================
// 1) concat embeddings into g_xa (side stream, overlapped with CSR build)
// ============================================================
__global__ void k_concat(const float* __restrict__ ue, const float* __restrict__ ie) {
    int i = blockIdx.x * blockDim.x + threadIdx.x;
    const int nu4 = NUM_USERS * H / 4;   // 1,600,000
    const int ni4 = NUM_ITEMS * H / 4;   //   800,000
    float4* xa = (float4*)g_xa;
    if (i < nu4) {
        xa[i] = ((const float4*)ue)[i];
    } else if (i < nu4 + ni4) {
        xa[i] = ((const float4*)ie)[i - nu4];
    }
}

// ============================================================
// 2) degree count — 4 edges per thread (g_cnt zero at entry)
// ============================================================
__global__ void k_count(const int* __restrict__ dst) {
    int i = (blockIdx.x * blockDim.x + threadIdx.x) * 4;
    if (i < NE) {
        int4 d = *(const int4*)&dst[i];
        atomicAdd(&g_cnt[d.x], 1);
        atomicAdd(&g_cnt[d.y], 1);
        atomicAdd(&g_cnt[d.z], 1);
        atomicAdd(&g_cnt[d.w], 1);
    }
}

// ============================================================
// 3) scans (3-phase); scan1 re-zeroes g_cnt for the next call/replay
// ============================================================
__global__ void k_scan1() {
    __shared__ __align__(16) int sdata[1024];
    int tid = threadIdx.x;
    int i = blockIdx.x * 1024 + tid;
    int v = 0;
    if (i < NN) { v = g_cnt[i]; g_cnt[i] = 0; }
    sdata[tid] = v;
    __syncthreads();
    #pragma unroll
    for (int ofs = 1; ofs < 1024; ofs <<= 1) {
        int t = (tid >= ofs) ? sdata[tid - ofs] : 0;
        __syncthreads();
        sdata[tid] += t;
        __syncthreads();
    }
    if (i < NN) g_off[i] = sdata[tid] - v;
    if (tid == 1023) g_psum[blockIdx.x] = sdata[1023];
}

__global__ void k_scan2() {
    __shared__ __align__(16) int sdata[256];
    int tid = threadIdx.x;
    int v = (tid < NTILES) ? g_psum[tid] : 0;
    sdata[tid] = v;
    __syncthreads();
    #pragma unroll
    for (int ofs = 1; ofs < 256; ofs <<= 1) {
        int t = (tid >= ofs) ? sdata[tid - ofs] : 0;
        __syncthreads();
        sdata[tid] += t;
        __syncthreads();
    }
    if (tid < NTILES) g_psum[tid] = sdata[tid] - v;
}

__global__ void k_scan3() {
    int i = blockIdx.x * blockDim.x + threadIdx.x;
    if (i < NN) {
        int o = g_off[i] + g_psum[blockIdx.x >> 2];
        g_off[i] = o;
        g_cur[i] = o;
    }
    if (i == 0) g_off[NN] = NE;
}

// ============================================================
// 4) bucket edges by dst — 4 edges per thread
// ============================================================
__global__ void k_bucket(const int* __restrict__ src, const int* __restrict__ dst) {
    int i = (blockIdx.x * blockDim.x + threadIdx.x) * 4;
    if (i < NE) {
        int4 d = *(const int4*)&dst[i];
        int4 s = *(const int4*)&src[i];
        int p0 = atomicAdd(&g_cur[d.x], 1);
        int p1 = atomicAdd(&g_cur[d.y], 1);
        int p2 = atomicAdd(&g_cur[d.z], 1);
        int p3 = atomicAdd(&g_cur[d.w], 1);
        g_srcs[p0] = s.x;
        g_srcs[p1] = s.y;
        g_srcs[p2] = s.z;
        g_srcs[p3] = s.w;
    }
}

// ============================================================
// 5) mean aggregation: warp per node, float2 lanes, 4-deep unroll, __ldcg rows
// ============================================================
__global__ void k_agg(const float* __restrict__ x) {
    int w = (blockIdx.x * blockDim.x + threadIdx.x) >> 5;
    if (w >= NN) return;
    int lane = threadIdx.x & 31;
    const float2* x2p = (const float2*)x;
    int s = g_off[w], e = g_off[w + 1];
    float2 a0 = make_float2(0.f, 0.f), a1 = make_float2(0.f, 0.f);
    float2 a2 = make_float2(0.f, 0.f), a3 = make_float2(0.f, 0.f);
    int i = s;
    for (; i + 3 < e; i += 4) {
        int s0 = __ldg(&g_srcs[i]);
        int s1 = __ldg(&g_srcs[i + 1]);
        int s2 = __ldg(&g_srcs[i + 2]);
        int s3 = __ldg(&g_srcs[i + 3]);
        float2 v0 = __ldcg(&x2p[s0 * 32 + lane]);
        float2 v1 = __ldcg(&x2p[s1 * 32 + lane]);
        float2 v2 = __ldcg(&x2p[s2 * 32 + lane]);
        float2 v3 = __ldcg(&x2p[s3 * 32 + lane]);
        a0.x += v0.x; a0.y += v0.y;
        a1.x += v1.x; a1.y += v1.y;
        a2.x += v2.x; a2.y += v2.y;
        a3.x += v3.x; a3.y += v3.y;
    }
    for (; i < e; i++) {
        int sn = __ldg(&g_srcs[i]);
        float2 v = __ldcg(&x2p[sn * 32 + lane]);
        a0.x += v.x; a0.y += v.y;
    }
    int c = e - s;
    float inv = 1.0f / (float)(c > 1 ? c : 1);
    float2 m;
    m.x = ((a0.x + a1.x) + (a2.x + a3.x)) * inv;
    m.y = ((a0.y + a1.y) + (a2.y + a3.y)) * inv;
    ((float2*)g_mean)[w * 32 + lane] = m;
}

// ============================================================
// 6) tensor-core layer GEMM (3xTF32):
//    xout = relu(mean @ Wl + xin @ Wr + b) — weights staged in smem
// ============================================================
__global__ __launch_bounds__(256) void k_gemm(
        const float* __restrict__ xin, float* __restrict__ xout,
        const float* __restrict__ Wl, const float* __restrict__ bl,
        const float* __restrict__ Wr) {
    extern __shared__ float smem[];
    float* sBhi = smem;              // [n=64][k=128] stride 132
    float* sBlo = smem + 64 * 132;

    int tid = threadIdx.x;
    for (int idx = tid; idx < 64 * 128; idx += 256) {
        int k = idx >> 6;
        int n = idx & 63;
        float v = (k < 64) ? Wl[k * 64 + n] : Wr[(k - 64) * 64 + n];
        uint32_t hb = f2tf32(v);
        float hi = __uint_as_float(hb);
        uint32_t lb = f2tf32(v - hi);
        sBhi[n * 132 + k] = __uint_as_float(hb);
        sBlo[n * 132 + k] = __uint_as_float(lb);
    }
    __syncthreads();

    int wid = tid >> 5, lane = tid & 31;
    int g = lane >> 2;
    int tig = lane & 3;

    float2 bias[8];
    #pragma unroll
    for (int n0 = 0; n0 < 8; n0++)
        bias[n0] = *(const float2*)&bl[n0 * 8 + 2 * tig];

    const float* Aops[2] = { g_mean, xin };
    int nwarp = gridDim.x * 8;

    for (int wt = blockIdx.x * 8 + wid; wt < NN / 16; wt += nwarp) {
        int r0 = wt * 16;
        float c[8][4];
        #pragma unroll
        for (int n0 = 0; n0 < 8; n0++)
            c[n0][0] = c[n0][1] = c[n0][2] = c[n0][3] = 0.f;

        #pragma unroll
        for (int op = 0; op < 2; op++) {
            const float* A = Aops[op];
            int kb = op * 64;
            #pragma unroll
            for (int ks = 0; ks < 8; ks++) {
                int col = ks * 8 + tig;
                float f0 = __ldg(&A[(r0 + g) * 64 + col]);
                float f1 = __ldg(&A[(r0 + g + 8) * 64 + col]);
                float f2 = __ldg(&A[(r0 + g) * 64 + col + 4]);
                float f3 = __ldg(&A[(r0 + g + 8) * 64 + col + 4]);
                uint32_t ah0 = f2tf32(f0), ah1 = f2tf32(f1);
                uint32_t ah2 = f2tf32(f2), ah3 = f2tf32(f3);
                uint32_t al0 = f2tf32(f0 - __uint_as_float(ah0));
                uint32_t al1 = f2tf32(f1 - __uint_as_float(ah1));
                uint32_t al2 = f2tf32(f2 - __uint_as_float(ah2));
                uint32_t al3 = f2tf32(f3 - __uint_as_float(ah3));
                int kk = kb + ks * 8;
                #pragma unroll
                for (int n0 = 0; n0 < 8; n0++) {
                    int nrow = (n0 * 8 + g) * 132 + kk + tig;
                    uint32_t bh0 = __float_as_uint(sBhi[nrow]);
                    uint32_t bh1 = __float_as_uint(sBhi[nrow + 4]);
                    uint32_t bl0 = __float_as_uint(sBlo[nrow]);
                    uint32_t bl1 = __float_as_uint(sBlo[nrow + 4]);
                    mma_tf32(c[n0], ah0, ah1, ah2, ah3, bh0, bh1);
                    mma_tf32(c[n0], ah0, ah1, ah2, ah3, bl0, bl1);
                    mma_tf32(c[n0], al0, al1, al2, al3, bh0, bh1);
                }
            }
        }

        #pragma unroll
        for (int n0 = 0; n0 < 8; n0++) {
            float2 o01, o23;
            o01.x = fmaxf(c[n0][0] + bias[n0].x, 0.f);
            o01.y = fmaxf(c[n0][1] + bias[n0].y, 0.f);
            o23.x = fmaxf(c[n0][2] + bias[n0].x, 0.f);
            o23.y = fmaxf(c[n0][3] + bias[n0].y, 0.f);
            int ccol = n0 * 8 + 2 * tig;
            *(float2*)&xout[(r0 + g) * 64 + ccol] = o01;
            *(float2*)&xout[(r0 + g + 8) * 64 + ccol] = o23;
        }
    }
}

// ============================================================
// 7) final MLP on tensor cores: warp owns 16 pairs.
//    Phase A: gather 16 pair rows (user||item, 128 f) into smem (stride 132).
//    Phase B: 3xTF32 m16n8k8 vs smem W1 hi/lo; relu; dot W2; tig-reduce; clip.
// ============================================================
__global__ __launch_bounds__(256) void k_mlp(
        const float* __restrict__ x,
        const int* __restrict__ uid, const int* __restrict__ iid,
        const float* __restrict__ W1, const float* __restrict__ b1,
        const float* __restrict__ W2, const float* __restrict__ b2,
        float* __restrict__ out) {
    extern __shared__ float smem[];
    float* sW1hi = smem;                       // [n=32][k=128] stride 132
    float* sW1lo = smem + 32 * 132;
    float* spair0 = smem + 2 * 32 * 132;       // 8 warps x [16][132]
    __shared__ __align__(16) float sW2[MLPH];
    __shared__ __align__(16) float sb1[MLPH];
    __shared__ float sb2;

    int tid = threadIdx.x;
    // stage + split W1: W1 is [128][32] row-major -> [n][k]
    for (int idx = tid; idx < 32 * 128; idx += 256) {
        int n = idx >> 7;        // 0..31
        int k = idx & 127;       // 0..127
        float v = W1[k * MLPH + n];
        uint32_t hb = f2tf32(v);
        float hi = __uint_as_float(hb);
        uint32_t lb = f2tf32(v - hi);
        sW1hi[n * 132 + k] = hi;
        sW1lo[n * 132 + k] = __uint_as_float(lb);
    }
    if (tid < MLPH) { sW2[tid] = W2[tid]; sb1[tid] = b1[tid]; }
    if (tid == 0) sb2 = b2[0];
    __syncthreads();

    int wid = tid >> 5, lane = tid & 31;
    int g = lane >> 2, tig = lane & 3;
    float* sp = spair0 + wid * (16 * 132);

    for (int wt = blockIdx.x * 8 + wid; wt < MLP_TILES; wt += gridDim.x * 8) {
        int p0 = wt * 16;

        // ---- phase A: gather 16 pairs ----
        #pragma unroll 1
        for (int j = 0; j < 16; j++) {
            int u = __ldg(&uid[p0 + j]);
            int it = __ldg(&iid[p0 + j]) + NUM_USERS;
            if (lane < 16) {
                float4 v = __ldg(&((const float4*)(x + (size_t)u * H))[lane]);
                *(float4*)&sp[j * 132 + lane * 4] = v;
            } else {
                float4 v = __ldg(&((const float4*)(x + (size_t)it * H))[lane - 16]);
                *(float4*)&sp[j * 132 + 64 + (lane - 16) * 4] = v;
            }
        }
        __syncwarp();

        // ---- phase B: MMA, K=128, N=32 ----
        float c[4][4];
        #pragma unroll
        for (int n0 = 0; n0 < 4; n0++)
            c[n0][0] = c[n0][1] = c[n0][2] = c[n0][3] = 0.f;

        #pragma unroll
        for (int ks = 0; ks < 16; ks++) {
            int col = ks * 8 + tig;
            float f0 = sp[g * 132 + col];
            float f1 = sp[(g + 8) * 132 + col];
            float f2 = sp[g * 132 + col + 4];
            float f3 = sp[(g + 8) * 132 + col + 4];
            uint32_t ah0 = f2tf32(f0), ah1 = f2tf32(f1);
            uint32_t ah2 = f2tf32(f2), ah3 = f2tf32(f3);
            uint32_t al0 = f2tf32(f0 - __uint_as_float(ah0));
            uint32_t al1 = f2tf32(f1 - __uint_as_float(ah1));
            uint32_t al2 = f2tf32(f2 - __uint_as_float(ah2));
            uint32_t al3 = f2tf32(f3 - __uint_as_float(ah3));
            int kk = ks * 8;
            #pragma unroll
            for (int n0 = 0; n0 < 4; n0++) {
                int nrow = (n0 * 8 + g) * 132 + kk + tig;
                uint32_t bh0 = __float_as_uint(sW1hi[nrow]);
                uint32_t bh1 = __float_as_uint(sW1hi[nrow + 4]);
                uint32_t bl0 = __float_as_uint(sW1lo[nrow]);
                uint32_t bl1 = __float_as_uint(sW1lo[nrow + 4]);
                mma_tf32(c[n0], ah0, ah1, ah2, ah3, bh0, bh1);
                mma_tf32(c[n0], ah0, ah1, ah2, ah3, bl0, bl1);
                mma_tf32(c[n0], al0, al1, al2, al3, bh0, bh1);
            }
        }

        // ---- epilogue: relu, dot W2, tig-reduce, clip ----
        float r0 = 0.f, r1 = 0.f;
        #pragma unroll
        for (int n0 = 0; n0 < 4; n0++) {
            int cc = n0 * 8 + 2 * tig;
            float w20 = sW2[cc], w21 = sW2[cc + 1];
            float bb0 = sb1[cc], bb1 = sb1[cc + 1];
            float h0 = fmaxf(c[n0][0] + bb0, 0.f);
            float h1 = fmaxf(c[n0][1] + bb1, 0.f);
            float h2 = fmaxf(c[n0][2] + bb0, 0.f);
            float h3 = fmaxf(c[n0][3] + bb1, 0.f);
            r0 += h0 * w20 + h1 * w21;
            r1 += h2 * w20 + h3 * w21;
        }
        r0 += __shfl_xor_sync(0xffffffffu, r0, 1);
        r0 += __shfl_xor_sync(0xffffffffu, r0, 2);
        r1 += __shfl_xor_sync(0xffffffffu, r1, 1);
        r1 += __shfl_xor_sync(0xffffffffu, r1, 2);
        if (tig == 0) {
            out[p0 + g]     = fminf(fmaxf(r0 + sb2, 1.0f), 5.0f);
            out[p0 + g + 8] = fminf(fmaxf(r1 + sb2, 1.0f), 5.0f);
        }
        __syncwarp();
    }
}

// ============================================================
// launch — R11 structure: concat || CSR build, serial layers
// ============================================================
extern "C" void kernel_launch(void* const* d_in, const int* in_sizes, int n_in,
                              void* d_out, int out_size) {
    (void)in_sizes; (void)n_in; (void)out_size;
    const int*   edge = (const int*)d_in[0];
    const int*   src  = edge;
    const int*   dst  = edge + NE;
    const int*   uid  = (const int*)d_in[1];
    const int*   iid  = (const int*)d_in[2];
    const float* ue   = (const float*)d_in[3];
    const float* ie   = (const float*)d_in[4];
    const float* Wl   = (const float*)d_in[5];
    const float* bl   = (const float*)d_in[6];
    const float* Wr   = (const float*)d_in[7];
    const float* W1   = (const float*)d_in[8];
    const float* b1   = (const float*)d_in[9];
    const float* W2   = (const float*)d_in[10];
    const float* b2   = (const float*)d_in[11];
    float* out = (float*)d_out;

    float *xa, *xb;
    cudaGetSymbolAddress((void**)&xa, g_xa);
    cudaGetSymbolAddress((void**)&xb, g_xb);

    cudaFuncSetAttribute(k_gemm, cudaFuncAttributeMaxDynamicSharedMemorySize, GEMM_SMEM);
    cudaFuncSetAttribute(k_mlp, cudaFuncAttributeMaxDynamicSharedMemorySize, MLP_SMEM);

    // R11-proven footprint: ONE side stream + two event handles
    cudaStream_t s1;
    cudaStreamCreateWithFlags(&s1, cudaStreamNonBlocking);
    cudaEvent_t e0, e1;
    cudaEventCreateWithFlags(&e0, cudaEventDisableTiming);
    cudaEventCreateWithFlags(&e1, cudaEventDisableTiming);

    // fork: concat on s1, CSR chain on stream 0
    cudaEventRecord(e0, 0);
    cudaStreamWaitEvent(s1, e0, 0);
    k_concat<<<(2400000 + 255) / 256, 256, 0, s1>>>(ue, ie);

    k_count<<<(NE / 4 + 255) / 256, 256>>>(dst);
    k_scan1<<<NTILES, 1024>>>();
    k_scan2<<<1, 256>>>();
    k_scan3<<<NTILES * 4, 256>>>();
    k_bucket<<<(NE / 4 + 255) / 256, 256>>>(src, dst);

    // join: layer 0 needs g_xa
    cudaEventRecord(e1, s1);
    cudaStreamWaitEvent(0, e1, 0);

    float* cur = xa;
    float* nxt = xb;
    for (int l = 0; l < 3; l++) {
        k_agg<<<(NN * 32 + 255) / 256, 256>>>(cur);
        k_gemm<<<GEMM_GRID, 256, GEMM_SMEM>>>(cur, nxt, Wl + l * H * H, bl + l * H, Wr + l * H * H);
        float* t = cur; cur = nxt; nxt = t;
    }

    k_mlp<<<MLP_GRID, 256, MLP_SMEM>>>(cur, uid, iid, W1, b1, W2, b2, out);
}